// round 2
// baseline (speedup 1.0000x reference)
#include <cuda_runtime.h>

#define N_NODES 100000
#define N_EDGES 1600000
#define C_IN    64
#define C_HID   64
#define C_OUT   32

// Scratch (device globals — no allocation allowed in kernel_launch)
__device__ __align__(16) float g_deg[N_NODES];              // deg, then dinv in place
__device__ __align__(16) float g_h1 [N_NODES * C_HID];      // x @ W1
__device__ __align__(16) float g_o1 [N_NODES * C_HID];      // layer-1 output (scatter target)
__device__ __align__(16) float g_h2 [N_NODES * C_OUT];      // relu(o1) @ W2

// ---------------------------------------------------------------------------
// K0: deg[i] = 1.0 (self-loop weight)
__global__ void k_init_deg() {
    int i = blockIdx.x * blockDim.x + threadIdx.x;
    if (i < N_NODES) g_deg[i] = 1.0f;
}

// K1: deg[dst] += ew[e]   (edge_index is int32: row 0 = src, row 1 = dst)
__global__ void k_deg(const int* __restrict__ ei, const float* __restrict__ ew) {
    int e = blockIdx.x * blockDim.x + threadIdx.x;
    if (e < N_EDGES) {
        int dst = ei[N_EDGES + e];
        atomicAdd(&g_deg[dst], ew[e]);
    }
}

// K2: dinv[i] = rsqrt(deg[i])   (deg >= 1 always from the self-loop)
__global__ void k_dinv() {
    int i = blockIdx.x * blockDim.x + threadIdx.x;
    if (i < N_NODES) g_deg[i] = rsqrtf(g_deg[i]);
}

// ---------------------------------------------------------------------------
// K3: h1 = x @ W1;  o1 = dinv^2 * h1 + b1  (self-loop term + bias, inits scatter target)
// block: 256 threads = 4 rows x 64 channels, 32 rows per block (8 iters), grid = 3125
__global__ void k_gemm1(const float* __restrict__ x,
                        const float* __restrict__ W1,
                        const float* __restrict__ b1) {
    __shared__ float Ws[64][64];
    __shared__ float xs[4][64];
    int tx = threadIdx.x & 63;   // channel
    int ty = threadIdx.x >> 6;   // row within group of 4

    for (int i = threadIdx.x; i < 64 * 64; i += 256)
        Ws[i >> 6][i & 63] = W1[i];
    float bias = b1[tx];

    int rowBase = blockIdx.x * 32;
    for (int it = 0; it < 8; ++it) {
        int row0 = rowBase + it * 4;
        __syncthreads();
        xs[ty][tx] = x[(row0 + ty) * 64 + tx];
        __syncthreads();
        int row = row0 + ty;
        float acc = 0.0f;
        #pragma unroll
        for (int k = 0; k < 64; ++k)
            acc = fmaf(xs[ty][k], Ws[k][tx], acc);
        g_h1[row * 64 + tx] = acc;
        float di = g_deg[row];
        g_o1[row * 64 + tx] = fmaf(di * di, acc, bias);
    }
}

// K4: edge scatter layer 1. 16 threads per edge, one float4 each.
__global__ void k_scatter1(const int* __restrict__ ei,
                           const float* __restrict__ ew) {
    long long t = (long long)blockIdx.x * blockDim.x + threadIdx.x;
    int e    = (int)(t >> 4);
    int lane = (int)(t & 15);
    if (e >= N_EDGES) return;
    int src = ei[e];
    int dst = ei[N_EDGES + e];
    float c = g_deg[src] * ew[e] * g_deg[dst];
    float4 v = *((const float4*)(g_h1 + src * 64) + lane);
    float* op = g_o1 + dst * 64 + lane * 4;
    asm volatile("red.global.add.v4.f32 [%0], {%1,%2,%3,%4};"
                 :: "l"(op), "f"(v.x * c), "f"(v.y * c), "f"(v.z * c), "f"(v.w * c)
                 : "memory");
}

// ---------------------------------------------------------------------------
// K5: h2 = relu(o1) @ W2;  d_out = dinv^2 * h2 + b2
// block: 256 threads = 8 rows x 32 channels, 32 rows per block (4 iters), grid = 3125
__global__ void k_gemm2(const float* __restrict__ W2,
                        const float* __restrict__ b2,
                        float* __restrict__ out) {
    __shared__ float Ws[64][32];
    __shared__ float xs[8][64];
    int tx = threadIdx.x & 31;   // channel
    int ty = threadIdx.x >> 5;   // row within group of 8

    for (int i = threadIdx.x; i < 64 * 32; i += 256)
        Ws[i >> 5][i & 31] = W2[i];
    float bias = b2[tx];

    int rowBase = blockIdx.x * 32;
    for (int it = 0; it < 4; ++it) {
        int row0 = rowBase + it * 8;
        __syncthreads();
        for (int i = threadIdx.x; i < 8 * 64; i += 256) {
            int r = i >> 6, k = i & 63;
            float v = g_o1[(row0 + r) * 64 + k];
            xs[r][k] = v > 0.0f ? v : 0.0f;
        }
        __syncthreads();
        int row = row0 + ty;
        float acc = 0.0f;
        #pragma unroll
        for (int k = 0; k < 64; ++k)
            acc = fmaf(xs[ty][k], Ws[k][tx], acc);
        g_h2[row * 32 + tx] = acc;
        float di = g_deg[row];
        out[row * 32 + tx] = fmaf(di * di, acc, bias);
    }
}

// K6: edge scatter layer 2. 8 threads per edge, one float4 each (32 channels).
__global__ void k_scatter2(const int* __restrict__ ei,
                           const float* __restrict__ ew,
                           float* __restrict__ out) {
    long long t = (long long)blockIdx.x * blockDim.x + threadIdx.x;
    int e    = (int)(t >> 3);
    int lane = (int)(t & 7);
    if (e >= N_EDGES) return;
    int src = ei[e];
    int dst = ei[N_EDGES + e];
    float c = g_deg[src] * ew[e] * g_deg[dst];
    float4 v = *((const float4*)(g_h2 + src * 32) + lane);
    float* op = out + dst * 32 + lane * 4;
    asm volatile("red.global.add.v4.f32 [%0], {%1,%2,%3,%4};"
                 :: "l"(op), "f"(v.x * c), "f"(v.y * c), "f"(v.z * c), "f"(v.w * c)
                 : "memory");
}

// ---------------------------------------------------------------------------
extern "C" void kernel_launch(void* const* d_in, const int* in_sizes, int n_in,
                              void* d_out, int out_size) {
    const float* x  = (const float*)d_in[0];
    const int*   ei = (const int*)d_in[1];      // int32 (JAX demotes int64)
    const float* ew = (const float*)d_in[2];
    const float* W1 = (const float*)d_in[3];
    const float* b1 = (const float*)d_in[4];
    const float* W2 = (const float*)d_in[5];
    const float* b2 = (const float*)d_in[6];
    float* out = (float*)d_out;

    k_init_deg<<<(N_NODES + 255) / 256, 256>>>();
    k_deg<<<(N_EDGES + 255) / 256, 256>>>(ei, ew);
    k_dinv<<<(N_NODES + 255) / 256, 256>>>();

    k_gemm1<<<N_NODES / 32, 256>>>(x, W1, b1);
    {   // 16 threads per edge
        long long total = (long long)N_EDGES * 16;
        int blocks = (int)((total + 255) / 256);
        k_scatter1<<<blocks, 256>>>(ei, ew);
    }
    k_gemm2<<<N_NODES / 32, 256>>>(W2, b2, out);
    {   // 8 threads per edge
        long long total = (long long)N_EDGES * 8;
        int blocks = (int)((total + 255) / 256);
        k_scatter2<<<blocks, 256>>>(ei, ew, out);
    }
}

// round 3
// speedup vs baseline: 1.4556x; 1.4556x over previous
#include <cuda_runtime.h>

#define N_NODES 100000
#define N_EDGES 1600000
#define C_IN    64
#define C_HID   64
#define C_OUT   32

#define SCAN_BLK 512
#define N_SCAN_BLOCKS ((N_NODES + SCAN_BLK - 1) / SCAN_BLK)   // 196

// ----- scratch (device globals; no runtime allocation) ----------------------
__device__ float g_deg[N_NODES];                 // deg, then dinv in place
__device__ int   g_cnt[N_NODES];                 // in-degree (edges only)
__device__ int   g_rs [N_NODES];                 // CSR row start
__device__ int   g_cur[N_NODES];                 // fill cursor
__device__ int   g_bsum[N_SCAN_BLOCKS];          // scan block sums

struct EdgeRec { int src; float w; };            // w = dinv[src] * ew
__device__ EdgeRec g_csr[N_EDGES];

__device__ __align__(16) float g_h1[N_NODES * C_HID];   // x @ W1
__device__ __align__(16) float g_o1[N_NODES * C_HID];   // relu(layer-1 out)
__device__ __align__(16) float g_h2[N_NODES * C_OUT];   // o1 @ W2

// ---------------------------------------------------------------------------
__global__ void k_init() {
    int i = blockIdx.x * blockDim.x + threadIdx.x;
    if (i < N_NODES) { g_deg[i] = 1.0f; g_cnt[i] = 0; }
}

// deg[dst] += ew ; cnt[dst]++    (edge_index int32: row0=src, row1=dst)
__global__ void k_deg(const int* __restrict__ ei, const float* __restrict__ ew) {
    int e = blockIdx.x * blockDim.x + threadIdx.x;
    if (e < N_EDGES) {
        int dst = ei[N_EDGES + e];
        atomicAdd(&g_deg[dst], ew[e]);
        atomicAdd(&g_cnt[dst], 1);
    }
}

__global__ void k_dinv() {
    int i = blockIdx.x * blockDim.x + threadIdx.x;
    if (i < N_NODES) g_deg[i] = rsqrtf(g_deg[i]);   // deg >= 1 (self-loop)
}

// ----- 3-kernel exclusive scan of g_cnt -> g_rs -----------------------------
__global__ void k_scanA() {
    __shared__ int s[SCAN_BLK];
    int i = blockIdx.x * SCAN_BLK + threadIdx.x;
    int v = (i < N_NODES) ? g_cnt[i] : 0;
    s[threadIdx.x] = v;
    __syncthreads();
    for (int off = 1; off < SCAN_BLK; off <<= 1) {
        int t = (threadIdx.x >= off) ? s[threadIdx.x - off] : 0;
        __syncthreads();
        s[threadIdx.x] += t;
        __syncthreads();
    }
    if (i < N_NODES) g_rs[i] = s[threadIdx.x] - v;          // exclusive
    if (threadIdx.x == SCAN_BLK - 1) g_bsum[blockIdx.x] = s[threadIdx.x];
}

__global__ void k_scanB() {   // single block of 256 (N_SCAN_BLOCKS=196)
    __shared__ int s[256];
    int v = (threadIdx.x < N_SCAN_BLOCKS) ? g_bsum[threadIdx.x] : 0;
    s[threadIdx.x] = v;
    __syncthreads();
    for (int off = 1; off < 256; off <<= 1) {
        int t = (threadIdx.x >= off) ? s[threadIdx.x - off] : 0;
        __syncthreads();
        s[threadIdx.x] += t;
        __syncthreads();
    }
    if (threadIdx.x < N_SCAN_BLOCKS) g_bsum[threadIdx.x] = s[threadIdx.x] - v;
}

__global__ void k_scanC() {
    int i = blockIdx.x * blockDim.x + threadIdx.x;
    if (i < N_NODES) {
        int r = g_rs[i] + g_bsum[i / SCAN_BLK];
        g_rs[i] = r;
        g_cur[i] = r;
    }
}

// CSR fill: csr[p] = {src, dinv[src]*ew}
__global__ void k_fill(const int* __restrict__ ei, const float* __restrict__ ew) {
    int e = blockIdx.x * blockDim.x + threadIdx.x;
    if (e < N_EDGES) {
        int src = ei[e];
        int dst = ei[N_EDGES + e];
        int p = atomicAdd(&g_cur[dst], 1);
        EdgeRec er; er.src = src; er.w = g_deg[src] * ew[e];
        g_csr[p] = er;
    }
}

// ---------------------------------------------------------------------------
// GEMM1: h1 = x @ W1. W column held in registers (float4 x16), xs via float4.
// block 256 = 64 channels x 4 ty; each thread 4 rows; 4 tiles of 16 rows/block.
__global__ void k_gemm1(const float* __restrict__ x, const float* __restrict__ W1) {
    __shared__ float4 xs[16][16];          // 16 rows x 64 floats
    int tx = threadIdx.x & 63;
    int ty = threadIdx.x >> 6;

    float4 w4[16];
    #pragma unroll
    for (int k4 = 0; k4 < 16; ++k4) {
        w4[k4].x = W1[(4 * k4 + 0) * 64 + tx];
        w4[k4].y = W1[(4 * k4 + 1) * 64 + tx];
        w4[k4].z = W1[(4 * k4 + 2) * 64 + tx];
        w4[k4].w = W1[(4 * k4 + 3) * 64 + tx];
    }

    int base = blockIdx.x * 64;
    for (int t = 0; t < 4; ++t) {
        int row0 = base + t * 16;
        __syncthreads();
        {
            int r = threadIdx.x >> 4, c = threadIdx.x & 15;
            if (row0 + r < N_NODES)
                xs[r][c] = ((const float4*)(x + (size_t)(row0 + r) * 64))[c];
        }
        __syncthreads();
        float acc[4] = {0.f, 0.f, 0.f, 0.f};
        #pragma unroll
        for (int k4 = 0; k4 < 16; ++k4) {
            float4 wv = w4[k4];
            #pragma unroll
            for (int r = 0; r < 4; ++r) {
                float4 xv = xs[ty * 4 + r][k4];
                acc[r] += xv.x * wv.x + xv.y * wv.y + xv.z * wv.z + xv.w * wv.w;
            }
        }
        #pragma unroll
        for (int r = 0; r < 4; ++r) {
            int row = row0 + ty * 4 + r;
            if (row < N_NODES) g_h1[(size_t)row * 64 + tx] = acc[r];
        }
    }
}

// Aggregation layer 1 (pull, no atomics): one warp per dst node.
// o1[dst] = relu( dinv[dst]*sum_e w_e*h1[src_e] + dinv[dst]^2*h1[dst] + b1 )
__global__ void k_agg1(const float* __restrict__ b1) {
    int w = (blockIdx.x * blockDim.x + threadIdx.x) >> 5;
    int lane = threadIdx.x & 31;
    if (w >= N_NODES) return;
    int beg = g_rs[w];
    int n   = g_cnt[w];
    float a0 = 0.f, a1 = 0.f;
    for (int i = 0; i < n; ++i) {
        EdgeRec er = g_csr[beg + i];
        const float* hp = g_h1 + (size_t)er.src * 64;
        a0 += er.w * hp[lane];
        a1 += er.w * hp[lane + 32];
    }
    float di = g_deg[w];
    const float* hs = g_h1 + (size_t)w * 64;
    a0 = di * a0 + di * di * hs[lane]      + b1[lane];
    a1 = di * a1 + di * di * hs[lane + 32] + b1[lane + 32];
    g_o1[(size_t)w * 64 + lane]      = fmaxf(a0, 0.f);
    g_o1[(size_t)w * 64 + lane + 32] = fmaxf(a1, 0.f);
}

// GEMM2: h2 = o1 @ W2. block 256 = 32 ch x 8 ty; 4 rows/thread; 4 tiles of 32 rows.
__global__ void k_gemm2(const float* __restrict__ W2) {
    __shared__ float4 xs[32][16];          // 32 rows x 64 floats
    int tx = threadIdx.x & 31;
    int ty = threadIdx.x >> 5;

    float4 w4[16];
    #pragma unroll
    for (int k4 = 0; k4 < 16; ++k4) {
        w4[k4].x = W2[(4 * k4 + 0) * 32 + tx];
        w4[k4].y = W2[(4 * k4 + 1) * 32 + tx];
        w4[k4].z = W2[(4 * k4 + 2) * 32 + tx];
        w4[k4].w = W2[(4 * k4 + 3) * 32 + tx];
    }

    int base = blockIdx.x * 128;
    for (int t = 0; t < 4; ++t) {
        int row0 = base + t * 32;
        __syncthreads();
        {
            int idx = threadIdx.x;           // 512 float4 loads, 2 per thread
            #pragma unroll
            for (int j = 0; j < 2; ++j, idx += 256) {
                int r = idx >> 4, c = idx & 15;
                if (row0 + r < N_NODES)
                    xs[r][c] = ((const float4*)(g_o1 + (size_t)(row0 + r) * 64))[c];
            }
        }
        __syncthreads();
        float acc[4] = {0.f, 0.f, 0.f, 0.f};
        #pragma unroll
        for (int k4 = 0; k4 < 16; ++k4) {
            float4 wv = w4[k4];
            #pragma unroll
            for (int r = 0; r < 4; ++r) {
                float4 xv = xs[ty * 4 + r][k4];
                acc[r] += xv.x * wv.x + xv.y * wv.y + xv.z * wv.z + xv.w * wv.w;
            }
        }
        #pragma unroll
        for (int r = 0; r < 4; ++r) {
            int row = row0 + ty * 4 + r;
            if (row < N_NODES) g_h2[(size_t)row * 32 + tx] = acc[r];
        }
    }
}

// Aggregation layer 2: one warp per dst, lane = channel (32).
__global__ void k_agg2(const float* __restrict__ b2, float* __restrict__ out) {
    int w = (blockIdx.x * blockDim.x + threadIdx.x) >> 5;
    int lane = threadIdx.x & 31;
    if (w >= N_NODES) return;
    int beg = g_rs[w];
    int n   = g_cnt[w];
    float a = 0.f;
    for (int i = 0; i < n; ++i) {
        EdgeRec er = g_csr[beg + i];
        a += er.w * g_h2[(size_t)er.src * 32 + lane];
    }
    float di = g_deg[w];
    a = di * a + di * di * g_h2[(size_t)w * 32 + lane] + b2[lane];
    out[(size_t)w * 32 + lane] = a;
}

// ---------------------------------------------------------------------------
extern "C" void kernel_launch(void* const* d_in, const int* in_sizes, int n_in,
                              void* d_out, int out_size) {
    const float* x  = (const float*)d_in[0];
    const int*   ei = (const int*)d_in[1];
    const float* ew = (const float*)d_in[2];
    const float* W1 = (const float*)d_in[3];
    const float* b1 = (const float*)d_in[4];
    const float* W2 = (const float*)d_in[5];
    const float* b2 = (const float*)d_in[6];
    float* out = (float*)d_out;

    k_init <<<(N_NODES + 255) / 256, 256>>>();
    k_deg  <<<(N_EDGES + 255) / 256, 256>>>(ei, ew);
    k_dinv <<<(N_NODES + 255) / 256, 256>>>();

    k_scanA<<<N_SCAN_BLOCKS, SCAN_BLK>>>();
    k_scanB<<<1, 256>>>();
    k_scanC<<<(N_NODES + 255) / 256, 256>>>();
    k_fill <<<(N_EDGES + 255) / 256, 256>>>(ei, ew);

    k_gemm1<<<(N_NODES + 63) / 64, 256>>>(x, W1);
    k_agg1 <<<(N_NODES * 32 + 255) / 256, 256>>>(b1);
    k_gemm2<<<(N_NODES + 127) / 128, 256>>>(W2);
    k_agg2 <<<(N_NODES * 32 + 255) / 256, 256>>>(b2, out);
}

// round 4
// speedup vs baseline: 1.5866x; 1.0899x over previous
#include <cuda_runtime.h>
#include <cuda_fp16.h>

#define N_NODES 100000
#define N_EDGES 1600000
#define C_IN    64
#define C_HID   64
#define C_OUT   32

#define SCAN_BLK 512
#define N_SCAN_BLOCKS ((N_NODES + SCAN_BLK - 1) / SCAN_BLK)   // 196

#define FIXP 16777216.0f   // 2^24 fixed-point scale for ew accumulation

// ----- scratch (device globals; no runtime allocation) ----------------------
__device__ unsigned long long g_pack[N_NODES];   // cnt<<40 | sum(ew)*2^24
__device__ float g_deg[N_NODES];                 // dinv
__device__ int   g_cnt[N_NODES];
__device__ int   g_rs [N_NODES];                 // CSR row start
__device__ int   g_cur[N_NODES];                 // fill cursor
__device__ int   g_bsum[N_SCAN_BLOCKS];

struct EdgeRec { int src; float w; };            // w = dinv[src] * ew
__device__ EdgeRec g_csr[N_EDGES];

__device__ __align__(16) __half g_h1h[N_NODES * C_HID];  // x @ W1   (fp16)
__device__ __align__(16) float  g_o1 [N_NODES * C_HID];  // relu(layer-1 out)
__device__ __align__(16) __half g_h2h[N_NODES * C_OUT];  // o1 @ W2  (fp16)

// ---------------------------------------------------------------------------
__global__ void k_init() {
    int i = blockIdx.x * blockDim.x + threadIdx.x;
    if (i < N_NODES) g_pack[i] = 0ull;
}

// one 64-bit atomic per edge: count + fixed-point weighted degree
__global__ void k_deg(const int* __restrict__ ei, const float* __restrict__ ew) {
    int e = blockIdx.x * blockDim.x + threadIdx.x;
    if (e < N_EDGES) {
        int dst = ei[N_EDGES + e];
        unsigned long long p =
            (1ull << 40) | (unsigned long long)(ew[e] * FIXP + 0.5f);
        atomicAdd(&g_pack[dst], p);
    }
}

// ----- scanA: unpack cnt + dinv, block-local exclusive scan -----------------
__global__ void k_scanA() {
    __shared__ int s[SCAN_BLK];
    int i = blockIdx.x * SCAN_BLK + threadIdx.x;
    int v = 0;
    if (i < N_NODES) {
        unsigned long long p = g_pack[i];
        v = (int)(p >> 40);
        g_cnt[i] = v;
        float deg = 1.0f + (float)(p & 0xFFFFFFFFFFull) * (1.0f / FIXP);
        g_deg[i] = rsqrtf(deg);
    }
    s[threadIdx.x] = v;
    __syncthreads();
    for (int off = 1; off < SCAN_BLK; off <<= 1) {
        int t = (threadIdx.x >= off) ? s[threadIdx.x - off] : 0;
        __syncthreads();
        s[threadIdx.x] += t;
        __syncthreads();
    }
    if (i < N_NODES) g_rs[i] = s[threadIdx.x] - v;          // exclusive
    if (threadIdx.x == SCAN_BLK - 1) g_bsum[blockIdx.x] = s[threadIdx.x];
}

__global__ void k_scanB() {   // single block of 256 (N_SCAN_BLOCKS=196)
    __shared__ int s[256];
    int v = (threadIdx.x < N_SCAN_BLOCKS) ? g_bsum[threadIdx.x] : 0;
    s[threadIdx.x] = v;
    __syncthreads();
    for (int off = 1; off < 256; off <<= 1) {
        int t = (threadIdx.x >= off) ? s[threadIdx.x - off] : 0;
        __syncthreads();
        s[threadIdx.x] += t;
        __syncthreads();
    }
    if (threadIdx.x < N_SCAN_BLOCKS) g_bsum[threadIdx.x] = s[threadIdx.x] - v;
}

__global__ void k_scanC() {
    int i = blockIdx.x * blockDim.x + threadIdx.x;
    if (i < N_NODES) {
        int r = g_rs[i] + g_bsum[i / SCAN_BLK];
        g_rs[i] = r;
        g_cur[i] = r;
    }
}

// CSR fill: csr[p] = {src, dinv[src]*ew}
__global__ void k_fill(const int* __restrict__ ei, const float* __restrict__ ew) {
    int e = blockIdx.x * blockDim.x + threadIdx.x;
    if (e < N_EDGES) {
        int src = ei[e];
        int dst = ei[N_EDGES + e];
        int p = atomicAdd(&g_cur[dst], 1);
        EdgeRec er; er.src = src; er.w = __ldg(&g_deg[src]) * ew[e];
        g_csr[p] = er;
    }
}

// ---------------------------------------------------------------------------
// GEMM1: h1 = x @ W1 (fp16 out). W column in registers, xs via float4 smem.
__global__ void k_gemm1(const float* __restrict__ x, const float* __restrict__ W1) {
    __shared__ float4 xs[16][16];          // 16 rows x 64 floats
    int tx = threadIdx.x & 63;
    int ty = threadIdx.x >> 6;

    float4 w4[16];
    #pragma unroll
    for (int k4 = 0; k4 < 16; ++k4) {
        w4[k4].x = W1[(4 * k4 + 0) * 64 + tx];
        w4[k4].y = W1[(4 * k4 + 1) * 64 + tx];
        w4[k4].z = W1[(4 * k4 + 2) * 64 + tx];
        w4[k4].w = W1[(4 * k4 + 3) * 64 + tx];
    }

    int base = blockIdx.x * 64;
    for (int t = 0; t < 4; ++t) {
        int row0 = base + t * 16;
        __syncthreads();
        {
            int r = threadIdx.x >> 4, c = threadIdx.x & 15;
            if (row0 + r < N_NODES)
                xs[r][c] = ((const float4*)(x + (size_t)(row0 + r) * 64))[c];
        }
        __syncthreads();
        float acc[4] = {0.f, 0.f, 0.f, 0.f};
        #pragma unroll
        for (int k4 = 0; k4 < 16; ++k4) {
            float4 wv = w4[k4];
            #pragma unroll
            for (int r = 0; r < 4; ++r) {
                float4 xv = xs[ty * 4 + r][k4];
                acc[r] += xv.x * wv.x + xv.y * wv.y + xv.z * wv.z + xv.w * wv.w;
            }
        }
        #pragma unroll
        for (int r = 0; r < 4; ++r) {
            int row = row0 + ty * 4 + r;
            if (row < N_NODES)
                g_h1h[(size_t)row * 64 + tx] = __float2half_rn(acc[r]);
        }
    }
}

// Aggregation layer 1: one warp per dst. lane covers channel pair (2l, 2l+1).
// Per edge: 8B broadcast rec + ONE 128B line (64 fp16 channels). Unroll x4.
__global__ void k_agg1(const float* __restrict__ b1) {
    int w = (blockIdx.x * blockDim.x + threadIdx.x) >> 5;
    int lane = threadIdx.x & 31;
    if (w >= N_NODES) return;
    int beg = g_rs[w];
    int n   = g_cnt[w];
    const __half2* h1v = (const __half2*)g_h1h;

    float a0 = 0.f, a1 = 0.f;
    int i = 0;
    for (; i + 3 < n; i += 4) {
        EdgeRec e0 = g_csr[beg + i + 0];
        EdgeRec e1 = g_csr[beg + i + 1];
        EdgeRec e2 = g_csr[beg + i + 2];
        EdgeRec e3 = g_csr[beg + i + 3];
        float2 f0 = __half22float2(__ldg(h1v + (size_t)e0.src * 32 + lane));
        float2 f1 = __half22float2(__ldg(h1v + (size_t)e1.src * 32 + lane));
        float2 f2 = __half22float2(__ldg(h1v + (size_t)e2.src * 32 + lane));
        float2 f3 = __half22float2(__ldg(h1v + (size_t)e3.src * 32 + lane));
        a0 += e0.w * f0.x + e1.w * f1.x + e2.w * f2.x + e3.w * f3.x;
        a1 += e0.w * f0.y + e1.w * f1.y + e2.w * f2.y + e3.w * f3.y;
    }
    for (; i < n; ++i) {
        EdgeRec er = g_csr[beg + i];
        float2 f = __half22float2(__ldg(h1v + (size_t)er.src * 32 + lane));
        a0 += er.w * f.x;
        a1 += er.w * f.y;
    }
    float di = g_deg[w];
    float2 hs = __half22float2(h1v[(size_t)w * 32 + lane]);
    float2 bb = ((const float2*)b1)[lane];
    a0 = di * a0 + di * di * hs.x + bb.x;
    a1 = di * a1 + di * di * hs.y + bb.y;
    ((float2*)g_o1)[(size_t)w * 32 + lane] =
        make_float2(fmaxf(a0, 0.f), fmaxf(a1, 0.f));
}

// GEMM2: h2 = o1 @ W2 (fp16 out). block 256 = 32 ch x 8 ty; 4 rows/thread.
__global__ void k_gemm2(const float* __restrict__ W2) {
    __shared__ float4 xs[32][16];          // 32 rows x 64 floats
    int tx = threadIdx.x & 31;
    int ty = threadIdx.x >> 5;

    float4 w4[16];
    #pragma unroll
    for (int k4 = 0; k4 < 16; ++k4) {
        w4[k4].x = W2[(4 * k4 + 0) * 32 + tx];
        w4[k4].y = W2[(4 * k4 + 1) * 32 + tx];
        w4[k4].z = W2[(4 * k4 + 2) * 32 + tx];
        w4[k4].w = W2[(4 * k4 + 3) * 32 + tx];
    }

    int base = blockIdx.x * 128;
    for (int t = 0; t < 4; ++t) {
        int row0 = base + t * 32;
        __syncthreads();
        {
            int idx = threadIdx.x;
            #pragma unroll
            for (int j = 0; j < 2; ++j, idx += 256) {
                int r = idx >> 4, c = idx & 15;
                if (row0 + r < N_NODES)
                    xs[r][c] = ((const float4*)(g_o1 + (size_t)(row0 + r) * 64))[c];
            }
        }
        __syncthreads();
        float acc[4] = {0.f, 0.f, 0.f, 0.f};
        #pragma unroll
        for (int k4 = 0; k4 < 16; ++k4) {
            float4 wv = w4[k4];
            #pragma unroll
            for (int r = 0; r < 4; ++r) {
                float4 xv = xs[ty * 4 + r][k4];
                acc[r] += xv.x * wv.x + xv.y * wv.y + xv.z * wv.z + xv.w * wv.w;
            }
        }
        #pragma unroll
        for (int r = 0; r < 4; ++r) {
            int row = row0 + ty * 4 + r;
            if (row < N_NODES)
                g_h2h[(size_t)row * 32 + tx] = __float2half_rn(acc[r]);
        }
    }
}

// Aggregation layer 2: one warp per dst; half-warps process alternating edges
// (32 fp16 channels = 16 half2 = one 64B gather per edge). Unroll x2 per half.
__global__ void k_agg2(const float* __restrict__ b2, float* __restrict__ out) {
    int w = (blockIdx.x * blockDim.x + threadIdx.x) >> 5;
    int lane = threadIdx.x & 31;
    if (w >= N_NODES) return;
    int half = lane >> 4;      // 0 or 1
    int c2   = lane & 15;      // half2 index within node
    int beg = g_rs[w];
    int n   = g_cnt[w];
    const __half2* h2v = (const __half2*)g_h2h;

    float a0 = 0.f, a1 = 0.f;
    int i = half;
    for (; i + 2 < n; i += 4) {         // this half handles i and i+2
        EdgeRec ea = g_csr[beg + i];
        EdgeRec eb = g_csr[beg + i + 2];
        float2 fa = __half22float2(__ldg(h2v + (size_t)ea.src * 16 + c2));
        float2 fb = __half22float2(__ldg(h2v + (size_t)eb.src * 16 + c2));
        a0 += ea.w * fa.x + eb.w * fb.x;
        a1 += ea.w * fa.y + eb.w * fb.y;
    }
    for (; i < n; i += 2) {
        EdgeRec er = g_csr[beg + i];
        float2 f = __half22float2(__ldg(h2v + (size_t)er.src * 16 + c2));
        a0 += er.w * f.x;
        a1 += er.w * f.y;
    }
    // combine the two half-warps
    a0 += __shfl_xor_sync(0xffffffffu, a0, 16);
    a1 += __shfl_xor_sync(0xffffffffu, a1, 16);

    if (half == 0) {
        float di = g_deg[w];
        float2 hs = __half22float2(h2v[(size_t)w * 16 + c2]);
        float2 bb = ((const float2*)b2)[c2];
        float o0 = di * a0 + di * di * hs.x + bb.x;
        float o1v = di * a1 + di * di * hs.y + bb.y;
        ((float2*)out)[(size_t)w * 16 + c2] = make_float2(o0, o1v);
    }
}

// ---------------------------------------------------------------------------
extern "C" void kernel_launch(void* const* d_in, const int* in_sizes, int n_in,
                              void* d_out, int out_size) {
    const float* x  = (const float*)d_in[0];
    const int*   ei = (const int*)d_in[1];
    const float* ew = (const float*)d_in[2];
    const float* W1 = (const float*)d_in[3];
    const float* b1 = (const float*)d_in[4];
    const float* W2 = (const float*)d_in[5];
    const float* b2 = (const float*)d_in[6];
    float* out = (float*)d_out;

    k_init <<<(N_NODES + 255) / 256, 256>>>();
    k_deg  <<<(N_EDGES + 255) / 256, 256>>>(ei, ew);

    k_scanA<<<N_SCAN_BLOCKS, SCAN_BLK>>>();
    k_scanB<<<1, 256>>>();
    k_scanC<<<(N_NODES + 255) / 256, 256>>>();
    k_fill <<<(N_EDGES + 255) / 256, 256>>>(ei, ew);

    k_gemm1<<<(N_NODES + 63) / 64, 256>>>(x, W1);
    k_agg1 <<<(N_NODES * 32 + 255) / 256, 256>>>(b1);
    k_gemm2<<<(N_NODES + 127) / 128, 256>>>(W2);
    k_agg2 <<<(N_NODES * 32 + 255) / 256, 256>>>(b2, out);
}